// round 15
// baseline (speedup 1.0000x reference)
#include <cuda_runtime.h>
#include <cuda_fp16.h>
#include <math.h>
#include <stdint.h>

#define Bb 32
#define Ss 2048
#define Hh 1024
#define Uu 1024
#define Mm (Bb*Ss)

// ---------------- device scratch (static, no runtime alloc) ----------------
__device__ float g_query[Bb*Uu];                     // q[b,u] = hidden_t@W2 + b2
__device__ float g_score[Bb*Ss];                     // combined scores -> weights
__device__ float g_spart[4][Bb*Ss];                  // per-u-pass partial scores
__device__ __align__(16) __half g_w1t_hi[Uu*Hh];     // W1^T fp16 [u][k]
__device__ __align__(16) __half g_a_hi[(size_t)Mm*Hh];  // hiddens fp16 (written by
                                                        // score ut==0 CTAs, read by context)

// ---------------- PTX helpers (non-'a' features only: valid on sm_103) -----
__device__ __forceinline__ void cp_async16(uint32_t dst, const void* src) {
    asm volatile("cp.async.cg.shared.global [%0], [%1], 16;\n"
                 :: "r"(dst), "l"(src) : "memory");
}
#define CP_COMMIT() asm volatile("cp.async.commit_group;\n" ::: "memory")
#define CP_WAIT0()  asm volatile("cp.async.wait_group 0;\n" ::: "memory")

__device__ __forceinline__ void ldsm4(uint32_t r[4], uint32_t addr) {
    asm volatile("ldmatrix.sync.aligned.m8n8.x4.shared.b16 {%0,%1,%2,%3}, [%4];"
                 : "=r"(r[0]), "=r"(r[1]), "=r"(r[2]), "=r"(r[3]) : "r"(addr));
}
__device__ __forceinline__ void mma16816(float c[4], const uint32_t a[4],
                                         uint32_t b0, uint32_t b1) {
    asm volatile("mma.sync.aligned.m16n8k16.row.col.f32.f16.f16.f32 "
                 "{%0,%1,%2,%3}, {%4,%5,%6,%7}, {%8,%9}, {%0,%1,%2,%3};"
                 : "+f"(c[0]), "+f"(c[1]), "+f"(c[2]), "+f"(c[3])
                 : "r"(a[0]), "r"(a[1]), "r"(a[2]), "r"(a[3]), "r"(b0), "r"(b1));
}

__device__ __forceinline__ float ftanh(float x) {
    const float cx = fminf(fmaxf(x, -9.f), 9.f);
    const float e  = __expf(2.f * cx);
    return __fdividef(e - 1.f, e + 1.f);
}

// ---------------- SMEM layout (score kernel) ----------------
#define OFF_BQ   0
#define OFF_VS   4096
#define OFF_SROW 8192
#define OFF_TILE 8704
// within one buffer: A sub0 16K | A sub1 16K | B sub0 32K | B sub1 32K
#define B_REG  32768
#define BUF_SZ 98304
#define SMEM_TOTAL (OFF_TILE + 2*BUF_SZ)   // 205312 bytes

#define KITER  8     // 8 double-chunks of K=128 (two 64-k subs each)
#define NTHR   512   // 16 warps: 4(M) x 4(N), warp tile 32 x 64

// ---------------- prep grid partition (w1t + query only) ----------------
#define NB_WT 512    // w1t: two 32x32 tiles per block
#define NB_Q  128    // query: (b, 256-u chunk)
#define NB_PREP (NB_WT + NB_Q)

// ---------------------------------------------------------------------------
// prep kernel: W1^T fp16 tiles + query[b,u] = hidden_t@W2 + b2
// ---------------------------------------------------------------------------
__global__ void __launch_bounds__(256)
prep_kernel(const float* __restrict__ W1,
            const float* __restrict__ hidden_t,
            const float* __restrict__ W2,
            const float* __restrict__ b2)
{
    __shared__ float shm[32 * 33];
    const int bid = blockIdx.x;
    const int tid = threadIdx.x;

    if (bid < NB_WT) {
        // -------- w1t: transpose+convert two 32x32 tiles --------
        const int t = bid * 2;
#pragma unroll
        for (int half = 0; half < 2; ++half) {
            const int tt = t + half;
            const int k0 = (tt & 31) * 32, u0 = (tt >> 5) * 32;
            const int x = tid & 31, y = tid >> 5;   // 32 x 8
#pragma unroll
            for (int i = 0; i < 32; i += 8)
                shm[(y + i) * 33 + x] = W1[(size_t)(k0 + y + i) * Uu + u0 + x];
            __syncthreads();
#pragma unroll
            for (int i = 0; i < 32; i += 8)
                g_w1t_hi[(size_t)(u0 + y + i) * Hh + k0 + x] =
                    __float2half_rn(shm[x * 33 + y + i]);
            __syncthreads();
        }
    } else {
        // -------- query: one (b, 256-u chunk) per block --------
        const int t = bid - NB_WT;
        const int b  = t >> 2;
        const int u  = (t & 3) * 256 + tid;
        float* ht = shm;
        for (int i = tid; i < Hh; i += 256) ht[i] = hidden_t[b * Hh + i];
        __syncthreads();
        float acc = b2[u];
#pragma unroll 8
        for (int h = 0; h < Hh; ++h)
            acc += ht[h] * W2[h * Uu + u];
        g_query[b * Uu + u] = acc;
    }
}

// ---------------------------------------------------------------------------
// A converter: one dchunk = 128 rows x 128 fp32 -> fp16, swizzled STS into
// the two 64-k sub-chunk regions. ut==0 CTAs also STG to g_a_hi for context.
// ---------------------------------------------------------------------------
__device__ __forceinline__ void convert_a(const float* __restrict__ hiddens,
                                          int row0, int k0, char* smem,
                                          uint32_t bufoff, int tid, bool wout)
{
#pragma unroll
    for (int i = 0; i < 8; ++i) {
        const int lin = i * NTHR + tid;
        const int r  = lin >> 5;        // 32 float4 per 128-float row
        const int c4 = lin & 31;
        const float4 v = *(const float4*)(hiddens + (size_t)(row0 + r) * Hh
                                          + k0 + c4 * 4);
        __half2 h01 = __halves2half2(__float2half_rn(v.x), __float2half_rn(v.y));
        __half2 h23 = __halves2half2(__float2half_rn(v.z), __float2half_rn(v.w));
        uint2 hv;
        hv.x = *reinterpret_cast<uint32_t*>(&h01);
        hv.y = *reinterpret_cast<uint32_t*>(&h23);
        const int s = c4 >> 4, c = c4 & 15;
        const uint32_t off = (uint32_t)(s * 16384 + r * 128
                            + (((c >> 1) * 16) ^ ((r & 7) * 16)) + (c & 1) * 8);
        *(uint2*)(smem + OFF_TILE + bufoff + off) = hv;
        if (wout)
            *(uint2*)(g_a_hi + (size_t)(row0 + r) * Hh + k0 + c4 * 4) = hv;
    }
}

// ---------------------------------------------------------------------------
// B loader: 256 u-rows x 128 k fp16 via cp.async (two 64-k sub-chunks)
// ---------------------------------------------------------------------------
__device__ __forceinline__ void load_b(int u0, int k0,
                                       uint32_t sb, uint32_t bufoff, int tid)
{
    const uint32_t base = sb + OFF_TILE + bufoff + B_REG;
#pragma unroll
    for (int s = 0; s < 2; ++s) {
#pragma unroll
        for (int i = 0; i < 4; ++i) {
            const int lin = i * NTHR + tid;
            const int n = lin >> 3, sg = lin & 7;
            const uint32_t off = (uint32_t)(n * 128 + ((sg * 16) ^ ((n & 7) * 16)));
            const size_t src = (size_t)(u0 + n) * Hh + (k0 + s * 64) + sg * 8;
            cp_async16(base + s * 32768 + off, g_w1t_hi + src);
        }
    }
}

// ---------------------------------------------------------------------------
// compute one 64-k sub-chunk: acc += A*B
// per warp: 32 rows (2 mt) x 64 cols (4 nt ldsm -> 8 n8)
// ---------------------------------------------------------------------------
__device__ __forceinline__ void compute_sub(float acc[2][8][4],
                                            const uint32_t a_base[2],
                                            const uint32_t b_base[4],
                                            int msk, int lk16,
                                            uint32_t aoff, uint32_t boff)
{
#pragma unroll
    for (int ks = 0; ks < 4; ++ks) {
        const uint32_t koff = (uint32_t)((ks * 32 + lk16) ^ msk);
        uint32_t ah[2][4], bh[4][4];
#pragma unroll
        for (int mt = 0; mt < 2; ++mt) ldsm4(ah[mt], a_base[mt] + aoff + koff);
#pragma unroll
        for (int nt = 0; nt < 4; ++nt) ldsm4(bh[nt], b_base[nt] + boff + koff);
#pragma unroll
        for (int mt = 0; mt < 2; ++mt)
#pragma unroll
            for (int nt = 0; nt < 4; ++nt) {
                mma16816(acc[mt][nt*2+0], ah[mt], bh[nt][0], bh[nt][2]);
                mma16816(acc[mt][nt*2+1], ah[mt], bh[nt][1], bh[nt][3]);
            }
    }
}

// ---------------------------------------------------------------------------
// fused score kernel: one CTA = (row-block, u-pass) unit
// grid 2048; ut minor so consecutive CTAs share A rows (L2 dedup of fp32 A)
// A converted in-kernel from fp32; ut==0 CTAs export fp16 A for context.
// ---------------------------------------------------------------------------
__global__ void __launch_bounds__(NTHR, 1)
score_kernel(const float* __restrict__ hiddens,
             const float* __restrict__ b1, const float* __restrict__ V)
{
    extern __shared__ char smem[];
    const uint32_t sb = (uint32_t)__cvta_generic_to_shared(smem);
    const int tid  = threadIdx.x;
    const int lane = tid & 31;
    const int wid  = tid >> 5;
    const int wm   = wid >> 2;      // 0..3  -> M offset 32*wm
    const int wn   = wid & 3;       // 0..3  -> N offset 64*wn
    const int ut     = blockIdx.x & 3;         // 0..3 (minor)
    const int rblock = blockIdx.x >> 2;        // 0..511
    const int row0 = rblock * 128;
    const int b    = rblock >> 4;
    const int u0   = ut * 256;
    const bool wout = (ut == 0);

    float* bqs  = (float*)(smem + OFF_BQ);     // bias+query for this pass (256)
    float* vss  = (float*)(smem + OFF_VS);
    float* srow = (float*)(smem + OFF_SROW);
    for (int i = tid; i < 256; i += NTHR) {
        bqs[i] = b1[u0 + i] + g_query[b * Uu + u0 + i];
        vss[i] = V[u0 + i];
    }
    if (tid < 128) srow[tid] = 0.f;

    // per-lane ldmatrix bases
    const int lrow = lane & 15;
    const int lk16 = (lane & 16);          // 0 or 16 bytes (k-halves)
    const int msk  = (lrow & 7) * 16;      // row-dependent xor mask
    uint32_t a_base[2], b_base[4];
#pragma unroll
    for (int mt = 0; mt < 2; ++mt)
        a_base[mt] = sb + OFF_TILE + (wm * 32 + mt * 16 + lrow) * 128;
#pragma unroll
    for (int nt = 0; nt < 4; ++nt)
        b_base[nt] = sb + OFF_TILE + (wn * 64 + nt * 16 + lrow) * 128;

    float acc[2][8][4];
#pragma unroll
    for (int mt = 0; mt < 2; ++mt)
#pragma unroll
        for (int n = 0; n < 8; ++n)
#pragma unroll
            for (int c = 0; c < 4; ++c) acc[mt][n][c] = 0.f;

    // prologue: dchunk 0 into buffer 0 (B via cp.async, A via LDG+cvt)
    load_b(u0, 0, sb, 0, tid);
    CP_COMMIT();
    convert_a(hiddens, row0, 0, smem, 0, tid, wout);

    for (int ki = 0; ki < KITER; ++ki) {
        const uint32_t bufoff = (uint32_t)(ki & 1) * BUF_SZ;

        CP_WAIT0();
        __syncthreads();   // data for ki visible; buffer ki-1 fully drained

        if (ki + 1 < KITER) {
            load_b(u0, (ki + 1) * 128, sb, bufoff ^ BUF_SZ, tid);
            CP_COMMIT();
            convert_a(hiddens, row0, (ki + 1) * 128, smem,
                      bufoff ^ BUF_SZ, tid, wout);
        }

        compute_sub(acc, a_base, b_base, msk, lk16,
                    bufoff, bufoff + B_REG);
        compute_sub(acc, a_base, b_base, msk, lk16,
                    bufoff + 16384, bufoff + B_REG + 32768);
    }

    // fused epilogue: tanh(key)*V partial row sums for this u-pass
    float sprt[4];
#pragma unroll
    for (int p = 0; p < 4; ++p) sprt[p] = 0.f;
#pragma unroll
    for (int mt = 0; mt < 2; ++mt)
#pragma unroll
        for (int n8 = 0; n8 < 8; ++n8) {
            const int u = wn * 64 + (n8 >> 1) * 16 + (n8 & 1) * 8 + (lane & 3) * 2;
            const float q0 = bqs[u],     v0 = vss[u];
            const float q1 = bqs[u + 1], v1 = vss[u + 1];
            sprt[mt*2+0] += ftanh(acc[mt][n8][0] + q0) * v0
                          + ftanh(acc[mt][n8][1] + q1) * v1;
            sprt[mt*2+1] += ftanh(acc[mt][n8][2] + q0) * v0
                          + ftanh(acc[mt][n8][3] + q1) * v1;
        }

    // reduce partial sums: quad shuffle then smem atomics across wn warps
    __syncthreads();
#pragma unroll
    for (int p = 0; p < 4; ++p) {
        float v = sprt[p];
        v += __shfl_xor_sync(0xffffffffu, v, 1);
        v += __shfl_xor_sync(0xffffffffu, v, 2);
        if ((lane & 3) == 0) {
            const int r = wm * 32 + (p >> 1) * 16 + (p & 1) * 8 + (lane >> 2);
            atomicAdd(&srow[r], v);
        }
    }
    __syncthreads();
    if (tid < 128) g_spart[ut][row0 + tid] = srow[tid];
}

// ---------------------------------------------------------------------------
// softmax over S per batch (summing the 4 pass partials);
// also zeroes the context region of d_out; weights -> d_out + g_score
// ---------------------------------------------------------------------------
__global__ void softmax_kernel(float* __restrict__ out)
{
    __shared__ float red[256];
    const int b = blockIdx.x;
    const int tid = threadIdx.x;
    float* sc = g_score + b * Ss;

    // zero context region (this batch's rows) before context_kernel atomics
    for (int i = tid; i < Hh; i += 256) out[b * Hh + i] = 0.f;

    float m = -1e30f;
    for (int i = tid; i < Ss; i += 256) {
        const int o = b * Ss + i;
        const float v = g_spart[0][o] + g_spart[1][o] + g_spart[2][o] + g_spart[3][o];
        sc[i] = v;
        m = fmaxf(m, v);
    }
    red[tid] = m;
    __syncthreads();
    for (int s = 128; s > 0; s >>= 1) {
        if (tid < s) red[tid] = fmaxf(red[tid], red[tid + s]);
        __syncthreads();
    }
    m = red[0];
    __syncthreads();

    float sum = 0.f;
    for (int i = tid; i < Ss; i += 256) {
        float e = expf(sc[i] - m);
        sc[i] = e;
        sum += e;
    }
    red[tid] = sum;
    __syncthreads();
    for (int s = 128; s > 0; s >>= 1) {
        if (tid < s) red[tid] += red[tid + s];
        __syncthreads();
    }
    const float inv = 1.f / red[0];
    __syncthreads();

    float* wout = out + Bb * Hh;
    for (int i = tid; i < Ss; i += 256) {
        const float w = sc[i] * inv;
        sc[i] = w;
        wout[b * Ss + i] = w;
    }
}

// ---------------------------------------------------------------------------
// context[b,h] = sum_s w[b,s] * hiddens[b,s,h]  (reads fp16 g_a_hi, written
// by the score kernel's ut==0 CTAs — stream order guarantees visibility)
// grid (B, 32 s-chunks), block 256; each thread owns 4 h values (uint2)
// ---------------------------------------------------------------------------
__global__ void __launch_bounds__(256)
context_kernel(float* __restrict__ out)
{
    const int b  = blockIdx.x;
    const int s0 = blockIdx.y * (Ss / 32);
    const int h4 = threadIdx.x;                    // 0..255 -> h = h4*4..h4*4+3

    const float* wp = g_score + b * Ss + s0;
    const uint2* hp = (const uint2*)(g_a_hi + (size_t)(b * Ss + s0) * Hh) + h4;

    float a0 = 0.f, a1 = 0.f, a2 = 0.f, a3 = 0.f;
#pragma unroll 8
    for (int s = 0; s < Ss / 32; ++s) {
        const float w = wp[s];
        const uint2 v = hp[(size_t)s * (Hh / 4)];
        const float2 p01 = __half22float2(*reinterpret_cast<const __half2*>(&v.x));
        const float2 p23 = __half22float2(*reinterpret_cast<const __half2*>(&v.y));
        a0 += w * p01.x;
        a1 += w * p01.y;
        a2 += w * p23.x;
        a3 += w * p23.y;
    }
    float* o = out + b * Hh + h4 * 4;
    atomicAdd(o + 0, a0);
    atomicAdd(o + 1, a1);
    atomicAdd(o + 2, a2);
    atomicAdd(o + 3, a3);
}

// ---------------------------------------------------------------------------
extern "C" void kernel_launch(void* const* d_in, const int* in_sizes, int n_in,
                              void* d_out, int out_size)
{
    const float* hidden_t = (const float*)d_in[0];
    const float* hiddens  = (const float*)d_in[1];
    const float* W1       = (const float*)d_in[2];
    const float* b1       = (const float*)d_in[3];
    const float* W2       = (const float*)d_in[4];
    const float* b2       = (const float*)d_in[5];
    const float* V        = (const float*)d_in[6];
    // d_in[7] = bV : constant shift, cancels in softmax -> unused

    float* out = (float*)d_out;

    cudaFuncSetAttribute(score_kernel,
                         cudaFuncAttributeMaxDynamicSharedMemorySize,
                         SMEM_TOTAL);

    prep_kernel<<<NB_PREP, 256>>>(W1, hidden_t, W2, b2);
    score_kernel<<<2048, NTHR, SMEM_TOTAL>>>(hiddens, b1, V);
    softmax_kernel<<<Bb, 256>>>(out);
    context_kernel<<<dim3(Bb, 32), 256>>>(out);
}

// round 16
// speedup vs baseline: 1.1939x; 1.1939x over previous
#include <cuda_runtime.h>
#include <cuda_fp16.h>
#include <math.h>
#include <stdint.h>

#define Bb 32
#define Ss 2048
#define Hh 1024
#define Uu 1024
#define Mm (Bb*Ss)

// ---------------- device scratch (static, no runtime alloc) ----------------
__device__ float g_query[Bb*Uu];                     // q[b,u] = hidden_t@W2 + b2
__device__ float g_score[Bb*Ss];                     // combined scores -> weights
__device__ float g_spart[4][Bb*Ss];                  // per-u-pass partial scores
__device__ __align__(16) __half g_w1t_hi[Uu*Hh];     // W1^T fp16 [u][k]
__device__ __align__(16) __half g_a_hi[(size_t)Mm*Hh];  // hiddens fp16 [row][k]

// ---------------- PTX helpers (non-'a' features only: valid on sm_103) -----
__device__ __forceinline__ void cp_async16(uint32_t dst, const void* src) {
    asm volatile("cp.async.cg.shared.global [%0], [%1], 16;\n"
                 :: "r"(dst), "l"(src) : "memory");
}
#define CP_COMMIT() asm volatile("cp.async.commit_group;\n" ::: "memory")
#define CP_WAIT0()  asm volatile("cp.async.wait_group 0;\n" ::: "memory")

__device__ __forceinline__ void ldsm4(uint32_t r[4], uint32_t addr) {
    asm volatile("ldmatrix.sync.aligned.m8n8.x4.shared.b16 {%0,%1,%2,%3}, [%4];"
                 : "=r"(r[0]), "=r"(r[1]), "=r"(r[2]), "=r"(r[3]) : "r"(addr));
}
__device__ __forceinline__ void mma16816(float c[4], const uint32_t a[4],
                                         uint32_t b0, uint32_t b1) {
    asm volatile("mma.sync.aligned.m16n8k16.row.col.f32.f16.f16.f32 "
                 "{%0,%1,%2,%3}, {%4,%5,%6,%7}, {%8,%9}, {%0,%1,%2,%3};"
                 : "+f"(c[0]), "+f"(c[1]), "+f"(c[2]), "+f"(c[3])
                 : "r"(a[0]), "r"(a[1]), "r"(a[2]), "r"(a[3]), "r"(b0), "r"(b1));
}

__device__ __forceinline__ float ftanh(float x) {
    const float cx = fminf(fmaxf(x, -9.f), 9.f);
    const float e  = __expf(2.f * cx);
    return __fdividef(e - 1.f, e + 1.f);
}

// ---------------- SMEM layout (score kernel) ----------------
#define OFF_BQ   0
#define OFF_VS   4096
#define OFF_SROW 8192
#define OFF_TILE 8704
// within one buffer: A sub0 16K | A sub1 16K | B sub0 32K | B sub1 32K
#define B_REG  32768
#define BUF_SZ 98304
#define SMEM_TOTAL (OFF_TILE + 2*BUF_SZ)   // 205312 bytes

#define KITER  8     // 8 double-chunks of K=128 (two 64-k subs each)
#define NTHR   512   // 16 warps: 4(M) x 4(N), warp tile 32 x 64

// ---------------- fused prep grid partition ----------------
#define NB_AH 4096   // a_half: 4096 float4 per block (16 per thread)
#define NB_WT 512    // w1t: two 32x32 tiles per block
#define NB_Q  128    // query: (b, 256-u chunk)
#define NB_PREP (NB_AH + NB_WT + NB_Q)

// ---------------------------------------------------------------------------
// fused prep kernel:
//   [0, NB_AH)              hiddens fp32 -> fp16 (16 float4 per thread)
//   [NB_AH, NB_AH+NB_WT)    W1^T fp16 (two 32x32 tiles per block)
//   [NB_AH+NB_WT, NB_PREP)  query[b,u] = hidden_t@W2 + b2
// ---------------------------------------------------------------------------
__global__ void __launch_bounds__(256)
prep_kernel(const float* __restrict__ hiddens,
            const float* __restrict__ W1,
            const float* __restrict__ hidden_t,
            const float* __restrict__ W2,
            const float* __restrict__ b2)
{
    __shared__ float shm[32 * 33];
    const int bid = blockIdx.x;
    const int tid = threadIdx.x;

    if (bid < NB_AH) {
        // -------- a_half: 4096 float4 per block, coalesced per iteration ----
        const size_t base = (size_t)bid * 4096 + tid;
#pragma unroll
        for (int j = 0; j < 16; ++j) {
            const size_t i = base + j * 256;
            const float4 v = ((const float4*)hiddens)[i];
            __half2 h01 = __halves2half2(__float2half_rn(v.x), __float2half_rn(v.y));
            __half2 h23 = __halves2half2(__float2half_rn(v.z), __float2half_rn(v.w));
            uint2 hv;
            hv.x = *reinterpret_cast<uint32_t*>(&h01);
            hv.y = *reinterpret_cast<uint32_t*>(&h23);
            ((uint2*)g_a_hi)[i] = hv;
        }
    } else if (bid < NB_AH + NB_WT) {
        // -------- w1t: transpose+convert two 32x32 tiles --------
        const int t = (bid - NB_AH) * 2;
#pragma unroll
        for (int half = 0; half < 2; ++half) {
            const int tt = t + half;
            const int k0 = (tt & 31) * 32, u0 = (tt >> 5) * 32;
            const int x = tid & 31, y = tid >> 5;   // 32 x 8
#pragma unroll
            for (int i = 0; i < 32; i += 8)
                shm[(y + i) * 33 + x] = W1[(size_t)(k0 + y + i) * Uu + u0 + x];
            __syncthreads();
#pragma unroll
            for (int i = 0; i < 32; i += 8)
                g_w1t_hi[(size_t)(u0 + y + i) * Hh + k0 + x] =
                    __float2half_rn(shm[x * 33 + y + i]);
            __syncthreads();
        }
    } else {
        // -------- query: one (b, 256-u chunk) per block --------
        const int t = bid - NB_AH - NB_WT;
        const int b  = t >> 2;
        const int u  = (t & 3) * 256 + tid;
        float* ht = shm;
        for (int i = tid; i < Hh; i += 256) ht[i] = hidden_t[b * Hh + i];
        __syncthreads();
        float acc = b2[u];
#pragma unroll 8
        for (int h = 0; h < Hh; ++h)
            acc += ht[h] * W2[h * Uu + u];
        g_query[b * Uu + u] = acc;
    }
}

// ---------------------------------------------------------------------------
// double-chunk loader: A (128 x 128) + B (256 x 128) fp16 via cp.async,
// stored as two 64-k sub-chunks (rows of 128B, xor-swizzled per 8-row group)
// ---------------------------------------------------------------------------
__device__ __forceinline__ void load_dchunk(int row0, int u0, int k0,
                                            uint32_t sb, uint32_t bufoff, int tid)
{
    const uint32_t base = sb + OFF_TILE + bufoff;
#pragma unroll
    for (int s = 0; s < 2; ++s) {
        // A sub: 128 rows x 8 segs -> 1024 segs / 512 thr = 2 each
#pragma unroll
        for (int i = 0; i < 2; ++i) {
            const int lin = i * NTHR + tid;
            const int n = lin >> 3, sg = lin & 7;
            const uint32_t off = (uint32_t)(n * 128 + ((sg * 16) ^ ((n & 7) * 16)));
            const size_t src = (size_t)(row0 + n) * Hh + (k0 + s * 64) + sg * 8;
            cp_async16(base + s * 16384 + off, g_a_hi + src);
        }
        // B sub: 256 rows x 8 segs -> 2048 segs / 512 thr = 4 each
#pragma unroll
        for (int i = 0; i < 4; ++i) {
            const int lin = i * NTHR + tid;
            const int n = lin >> 3, sg = lin & 7;
            const uint32_t off = (uint32_t)(n * 128 + ((sg * 16) ^ ((n & 7) * 16)));
            const size_t src = (size_t)(u0 + n) * Hh + (k0 + s * 64) + sg * 8;
            cp_async16(base + B_REG + s * 32768 + off, g_w1t_hi + src);
        }
    }
}

// ---------------------------------------------------------------------------
// compute one 64-k sub-chunk: acc += A*B
// per warp: 32 rows (2 mt) x 64 cols (4 nt ldsm -> 8 n8)
// ---------------------------------------------------------------------------
__device__ __forceinline__ void compute_sub(float acc[2][8][4],
                                            const uint32_t a_base[2],
                                            const uint32_t b_base[4],
                                            int msk, int lk16,
                                            uint32_t aoff, uint32_t boff)
{
#pragma unroll
    for (int ks = 0; ks < 4; ++ks) {
        const uint32_t koff = (uint32_t)((ks * 32 + lk16) ^ msk);
        uint32_t ah[2][4], bh[4][4];
#pragma unroll
        for (int mt = 0; mt < 2; ++mt) ldsm4(ah[mt], a_base[mt] + aoff + koff);
#pragma unroll
        for (int nt = 0; nt < 4; ++nt) ldsm4(bh[nt], b_base[nt] + boff + koff);
#pragma unroll
        for (int mt = 0; mt < 2; ++mt)
#pragma unroll
            for (int nt = 0; nt < 4; ++nt) {
                mma16816(acc[mt][nt*2+0], ah[mt], bh[nt][0], bh[nt][2]);
                mma16816(acc[mt][nt*2+1], ah[mt], bh[nt][1], bh[nt][3]);
            }
    }
}

// ---------------------------------------------------------------------------
// fused score kernel: one CTA = (row-block, u-pass) unit
// grid 2048; ut is the MINOR index so consecutive CTAs share A rows (L2 dedup)
// partial[row] = sum_{u in pass} tanh(hiddens@W1 + b1 + q)[u] * V[u]
// ---------------------------------------------------------------------------
__global__ void __launch_bounds__(NTHR, 1)
score_kernel(const float* __restrict__ b1, const float* __restrict__ V)
{
    extern __shared__ char smem[];
    const uint32_t sb = (uint32_t)__cvta_generic_to_shared(smem);
    const int tid  = threadIdx.x;
    const int lane = tid & 31;
    const int wid  = tid >> 5;
    const int wm   = wid >> 2;      // 0..3  -> M offset 32*wm
    const int wn   = wid & 3;       // 0..3  -> N offset 64*wn
    const int ut     = blockIdx.x & 3;         // 0..3 (minor)
    const int rblock = blockIdx.x >> 2;        // 0..511
    const int row0 = rblock * 128;
    const int b    = rblock >> 4;
    const int u0   = ut * 256;

    float* bqs  = (float*)(smem + OFF_BQ);     // bias+query for this pass (256)
    float* vss  = (float*)(smem + OFF_VS);
    float* srow = (float*)(smem + OFF_SROW);
    for (int i = tid; i < 256; i += NTHR) {
        bqs[i] = b1[u0 + i] + g_query[b * Uu + u0 + i];
        vss[i] = V[u0 + i];
    }
    if (tid < 128) srow[tid] = 0.f;

    // per-lane ldmatrix bases
    const int lrow = lane & 15;
    const int lk16 = (lane & 16);          // 0 or 16 bytes (k-halves)
    const int msk  = (lrow & 7) * 16;      // row-dependent xor mask
    uint32_t a_base[2], b_base[4];
#pragma unroll
    for (int mt = 0; mt < 2; ++mt)
        a_base[mt] = sb + OFF_TILE + (wm * 32 + mt * 16 + lrow) * 128;
#pragma unroll
    for (int nt = 0; nt < 4; ++nt)
        b_base[nt] = sb + OFF_TILE + (wn * 64 + nt * 16 + lrow) * 128;

    float acc[2][8][4];
#pragma unroll
    for (int mt = 0; mt < 2; ++mt)
#pragma unroll
        for (int n = 0; n < 8; ++n)
#pragma unroll
            for (int c = 0; c < 4; ++c) acc[mt][n][c] = 0.f;

    // prologue: double-chunk 0 into buffer 0
    load_dchunk(row0, u0, 0, sb, 0, tid);
    CP_COMMIT();

    for (int ki = 0; ki < KITER; ++ki) {
        const uint32_t bufoff = (uint32_t)(ki & 1) * BUF_SZ;

        CP_WAIT0();
        __syncthreads();   // data for ki visible; buffer ki-1 fully drained

        if (ki + 1 < KITER) {
            load_dchunk(row0, u0, (ki + 1) * 128, sb, bufoff ^ BUF_SZ, tid);
            CP_COMMIT();
        }

        compute_sub(acc, a_base, b_base, msk, lk16,
                    bufoff, bufoff + B_REG);
        compute_sub(acc, a_base, b_base, msk, lk16,
                    bufoff + 16384, bufoff + B_REG + 32768);
    }

    // fused epilogue: tanh(key)*V partial row sums for this u-pass
    float sprt[4];
#pragma unroll
    for (int p = 0; p < 4; ++p) sprt[p] = 0.f;
#pragma unroll
    for (int mt = 0; mt < 2; ++mt)
#pragma unroll
        for (int n8 = 0; n8 < 8; ++n8) {
            const int u = wn * 64 + (n8 >> 1) * 16 + (n8 & 1) * 8 + (lane & 3) * 2;
            const float q0 = bqs[u],     v0 = vss[u];
            const float q1 = bqs[u + 1], v1 = vss[u + 1];
            sprt[mt*2+0] += ftanh(acc[mt][n8][0] + q0) * v0
                          + ftanh(acc[mt][n8][1] + q1) * v1;
            sprt[mt*2+1] += ftanh(acc[mt][n8][2] + q0) * v0
                          + ftanh(acc[mt][n8][3] + q1) * v1;
        }

    // reduce partial sums: quad shuffle then smem atomics across wn warps
    __syncthreads();
#pragma unroll
    for (int p = 0; p < 4; ++p) {
        float v = sprt[p];
        v += __shfl_xor_sync(0xffffffffu, v, 1);
        v += __shfl_xor_sync(0xffffffffu, v, 2);
        if ((lane & 3) == 0) {
            const int r = wm * 32 + (p >> 1) * 16 + (p & 1) * 8 + (lane >> 2);
            atomicAdd(&srow[r], v);
        }
    }
    __syncthreads();
    if (tid < 128) g_spart[ut][row0 + tid] = srow[tid];
}

// ---------------------------------------------------------------------------
// softmax over S per batch (summing the 4 pass partials);
// also zeroes the context region of d_out; weights -> d_out + g_score
// ---------------------------------------------------------------------------
__global__ void softmax_kernel(float* __restrict__ out)
{
    __shared__ float red[256];
    const int b = blockIdx.x;
    const int tid = threadIdx.x;
    float* sc = g_score + b * Ss;

    // zero context region (this batch's rows) before context_kernel atomics
    for (int i = tid; i < Hh; i += 256) out[b * Hh + i] = 0.f;

    float m = -1e30f;
    for (int i = tid; i < Ss; i += 256) {
        const int o = b * Ss + i;
        const float v = g_spart[0][o] + g_spart[1][o] + g_spart[2][o] + g_spart[3][o];
        sc[i] = v;
        m = fmaxf(m, v);
    }
    red[tid] = m;
    __syncthreads();
    for (int s = 128; s > 0; s >>= 1) {
        if (tid < s) red[tid] = fmaxf(red[tid], red[tid + s]);
        __syncthreads();
    }
    m = red[0];
    __syncthreads();

    float sum = 0.f;
    for (int i = tid; i < Ss; i += 256) {
        float e = expf(sc[i] - m);
        sc[i] = e;
        sum += e;
    }
    red[tid] = sum;
    __syncthreads();
    for (int s = 128; s > 0; s >>= 1) {
        if (tid < s) red[tid] += red[tid + s];
        __syncthreads();
    }
    const float inv = 1.f / red[0];
    __syncthreads();

    float* wout = out + Bb * Hh;
    for (int i = tid; i < Ss; i += 256) {
        const float w = sc[i] * inv;
        sc[i] = w;
        wout[b * Ss + i] = w;
    }
}

// ---------------------------------------------------------------------------
// context[b,h] = sum_s w[b,s] * hiddens[b,s,h]  (reads fp16 g_a_hi)
// grid (B, 64 s-chunks), block 256; each thread owns 4 h values (uint2)
// ---------------------------------------------------------------------------
__global__ void __launch_bounds__(256)
context_kernel(float* __restrict__ out)
{
    const int b  = blockIdx.x;
    const int s0 = blockIdx.y * (Ss / 64);
    const int h4 = threadIdx.x;                    // 0..255 -> h = h4*4..h4*4+3

    const float* wp = g_score + b * Ss + s0;
    const uint2* hp = (const uint2*)(g_a_hi + (size_t)(b * Ss + s0) * Hh) + h4;

    float a0 = 0.f, a1 = 0.f, a2 = 0.f, a3 = 0.f;
#pragma unroll 8
    for (int s = 0; s < Ss / 64; ++s) {
        const float w = wp[s];
        const uint2 v = hp[(size_t)s * (Hh / 4)];
        const float2 p01 = __half22float2(*reinterpret_cast<const __half2*>(&v.x));
        const float2 p23 = __half22float2(*reinterpret_cast<const __half2*>(&v.y));
        a0 += w * p01.x;
        a1 += w * p01.y;
        a2 += w * p23.x;
        a3 += w * p23.y;
    }
    float* o = out + b * Hh + h4 * 4;
    atomicAdd(o + 0, a0);
    atomicAdd(o + 1, a1);
    atomicAdd(o + 2, a2);
    atomicAdd(o + 3, a3);
}

// ---------------------------------------------------------------------------
extern "C" void kernel_launch(void* const* d_in, const int* in_sizes, int n_in,
                              void* d_out, int out_size)
{
    const float* hidden_t = (const float*)d_in[0];
    const float* hiddens  = (const float*)d_in[1];
    const float* W1       = (const float*)d_in[2];
    const float* b1       = (const float*)d_in[3];
    const float* W2       = (const float*)d_in[4];
    const float* b2       = (const float*)d_in[5];
    const float* V        = (const float*)d_in[6];
    // d_in[7] = bV : constant shift, cancels in softmax -> unused

    float* out = (float*)d_out;

    cudaFuncSetAttribute(score_kernel,
                         cudaFuncAttributeMaxDynamicSharedMemorySize,
                         SMEM_TOTAL);

    prep_kernel<<<NB_PREP, 256>>>(hiddens, W1, hidden_t, W2, b2);
    score_kernel<<<2048, NTHR, SMEM_TOTAL>>>(b1, V);
    softmax_kernel<<<Bb, 256>>>(out);
    context_kernel<<<dim3(Bb, 64), 256>>>(out);
}

// round 17
// speedup vs baseline: 1.2208x; 1.0225x over previous
#include <cuda_runtime.h>
#include <cuda_fp16.h>
#include <math.h>
#include <stdint.h>

#define Bb 32
#define Ss 2048
#define Hh 1024
#define Uu 1024
#define Mm (Bb*Ss)

// ---------------- device scratch (static, no runtime alloc) ----------------
__device__ float g_query[Bb*Uu];                     // q[b,u] = hidden_t@W2 + b2
__device__ float g_score[Bb*Ss];                     // combined scores -> weights
__device__ float g_spart[4][Bb*Ss];                  // per-u-pass partial scores
__device__ __align__(16) __half g_w1t_hi[Uu*Hh];     // W1^T fp16 [u][k]
__device__ __align__(16) __half g_a_hi[(size_t)Mm*Hh];  // hiddens fp16 [row][k]

// ---------------- PTX helpers (non-'a' features only: valid on sm_103) -----
__device__ __forceinline__ void cp_async16(uint32_t dst, const void* src) {
    asm volatile("cp.async.cg.shared.global [%0], [%1], 16;\n"
                 :: "r"(dst), "l"(src) : "memory");
}
#define CP_COMMIT() asm volatile("cp.async.commit_group;\n" ::: "memory")
#define CP_WAIT0()  asm volatile("cp.async.wait_group 0;\n" ::: "memory")

__device__ __forceinline__ void ldsm4(uint32_t r[4], uint32_t addr) {
    asm volatile("ldmatrix.sync.aligned.m8n8.x4.shared.b16 {%0,%1,%2,%3}, [%4];"
                 : "=r"(r[0]), "=r"(r[1]), "=r"(r[2]), "=r"(r[3]) : "r"(addr));
}
__device__ __forceinline__ void mma16816(float c[4], const uint32_t a[4],
                                         uint32_t b0, uint32_t b1) {
    asm volatile("mma.sync.aligned.m16n8k16.row.col.f32.f16.f16.f32 "
                 "{%0,%1,%2,%3}, {%4,%5,%6,%7}, {%8,%9}, {%0,%1,%2,%3};"
                 : "+f"(c[0]), "+f"(c[1]), "+f"(c[2]), "+f"(c[3])
                 : "r"(a[0]), "r"(a[1]), "r"(a[2]), "r"(a[3]), "r"(b0), "r"(b1));
}

__device__ __forceinline__ float ftanh(float x) {
    const float cx = fminf(fmaxf(x, -9.f), 9.f);
    const float e  = __expf(2.f * cx);
    return __fdividef(e - 1.f, e + 1.f);
}

// ---------------- SMEM layout (score kernel) ----------------
#define OFF_BQ   0
#define OFF_VS   4096
#define OFF_SROW 8192
#define OFF_TILE 8704
// within one buffer: A sub0 16K | A sub1 16K | B sub0 32K | B sub1 32K
#define B_REG  32768
#define BUF_SZ 98304
#define SMEM_TOTAL (OFF_TILE + 2*BUF_SZ)   // 205312 bytes

#define KITER  8     // 8 double-chunks of K=128 (two 64-k subs each)
#define NTHR   512   // 16 warps: 4(M) x 4(N), warp tile 32 x 64

// ---------------- fused prep grid partition (latency-bound parts FIRST) ----
#define NB_WT 512    // w1t: two 32x32 tiles per block
#define NB_Q  128    // query: (b, 256-u chunk)
#define NB_AH 4096   // a_half: 4096 float4 per block (16 per thread)
#define NB_PREP (NB_WT + NB_Q + NB_AH)

// ---------------------------------------------------------------------------
// fused prep kernel (w1t/query dispatched first, hidden under a_half stream):
//   [0, NB_WT)                    W1^T fp16 (two 32x32 tiles per block)
//   [NB_WT, NB_WT+NB_Q)           query[b,u] = hidden_t@W2 + b2
//   [NB_WT+NB_Q, NB_PREP)         hiddens fp32 -> fp16 (16 float4 per thread)
// ---------------------------------------------------------------------------
__global__ void __launch_bounds__(256)
prep_kernel(const float* __restrict__ hiddens,
            const float* __restrict__ W1,
            const float* __restrict__ hidden_t,
            const float* __restrict__ W2,
            const float* __restrict__ b2)
{
    __shared__ float shm[32 * 33];
    const int bid = blockIdx.x;
    const int tid = threadIdx.x;

    if (bid < NB_WT) {
        // -------- w1t: transpose+convert two 32x32 tiles --------
        const int t = bid * 2;
#pragma unroll
        for (int half = 0; half < 2; ++half) {
            const int tt = t + half;
            const int k0 = (tt & 31) * 32, u0 = (tt >> 5) * 32;
            const int x = tid & 31, y = tid >> 5;   // 32 x 8
#pragma unroll
            for (int i = 0; i < 32; i += 8)
                shm[(y + i) * 33 + x] = W1[(size_t)(k0 + y + i) * Uu + u0 + x];
            __syncthreads();
#pragma unroll
            for (int i = 0; i < 32; i += 8)
                g_w1t_hi[(size_t)(u0 + y + i) * Hh + k0 + x] =
                    __float2half_rn(shm[x * 33 + y + i]);
            __syncthreads();
        }
    } else if (bid < NB_WT + NB_Q) {
        // -------- query: one (b, 256-u chunk) per block --------
        const int t = bid - NB_WT;
        const int b  = t >> 2;
        const int u  = (t & 3) * 256 + tid;
        float* ht = shm;
        for (int i = tid; i < Hh; i += 256) ht[i] = hidden_t[b * Hh + i];
        __syncthreads();
        float acc = b2[u];
#pragma unroll 8
        for (int h = 0; h < Hh; ++h)
            acc += ht[h] * W2[h * Uu + u];
        g_query[b * Uu + u] = acc;
    } else {
        // -------- a_half: 4096 float4 per block, coalesced per iteration ----
        const size_t base = (size_t)(bid - NB_WT - NB_Q) * 4096 + tid;
#pragma unroll
        for (int j = 0; j < 16; ++j) {
            const size_t i = base + j * 256;
            const float4 v = ((const float4*)hiddens)[i];
            __half2 h01 = __halves2half2(__float2half_rn(v.x), __float2half_rn(v.y));
            __half2 h23 = __halves2half2(__float2half_rn(v.z), __float2half_rn(v.w));
            uint2 hv;
            hv.x = *reinterpret_cast<uint32_t*>(&h01);
            hv.y = *reinterpret_cast<uint32_t*>(&h23);
            ((uint2*)g_a_hi)[i] = hv;
        }
    }
}

// ---------------------------------------------------------------------------
// double-chunk loader: A (128 x 128) + B (256 x 128) fp16 via cp.async,
// stored as two 64-k sub-chunks (rows of 128B, xor-swizzled per 8-row group)
// ---------------------------------------------------------------------------
__device__ __forceinline__ void load_dchunk(int row0, int u0, int k0,
                                            uint32_t sb, uint32_t bufoff, int tid)
{
    const uint32_t base = sb + OFF_TILE + bufoff;
#pragma unroll
    for (int s = 0; s < 2; ++s) {
        // A sub: 128 rows x 8 segs -> 1024 segs / 512 thr = 2 each
#pragma unroll
        for (int i = 0; i < 2; ++i) {
            const int lin = i * NTHR + tid;
            const int n = lin >> 3, sg = lin & 7;
            const uint32_t off = (uint32_t)(n * 128 + ((sg * 16) ^ ((n & 7) * 16)));
            const size_t src = (size_t)(row0 + n) * Hh + (k0 + s * 64) + sg * 8;
            cp_async16(base + s * 16384 + off, g_a_hi + src);
        }
        // B sub: 256 rows x 8 segs -> 2048 segs / 512 thr = 4 each
#pragma unroll
        for (int i = 0; i < 4; ++i) {
            const int lin = i * NTHR + tid;
            const int n = lin >> 3, sg = lin & 7;
            const uint32_t off = (uint32_t)(n * 128 + ((sg * 16) ^ ((n & 7) * 16)));
            const size_t src = (size_t)(u0 + n) * Hh + (k0 + s * 64) + sg * 8;
            cp_async16(base + B_REG + s * 32768 + off, g_w1t_hi + src);
        }
    }
}

// ---------------------------------------------------------------------------
// compute one 64-k sub-chunk: acc += A*B
// per warp: 32 rows (2 mt) x 64 cols (4 nt ldsm -> 8 n8)
// ---------------------------------------------------------------------------
__device__ __forceinline__ void compute_sub(float acc[2][8][4],
                                            const uint32_t a_base[2],
                                            const uint32_t b_base[4],
                                            int msk, int lk16,
                                            uint32_t aoff, uint32_t boff)
{
#pragma unroll
    for (int ks = 0; ks < 4; ++ks) {
        const uint32_t koff = (uint32_t)((ks * 32 + lk16) ^ msk);
        uint32_t ah[2][4], bh[4][4];
#pragma unroll
        for (int mt = 0; mt < 2; ++mt) ldsm4(ah[mt], a_base[mt] + aoff + koff);
#pragma unroll
        for (int nt = 0; nt < 4; ++nt) ldsm4(bh[nt], b_base[nt] + boff + koff);
#pragma unroll
        for (int mt = 0; mt < 2; ++mt)
#pragma unroll
            for (int nt = 0; nt < 4; ++nt) {
                mma16816(acc[mt][nt*2+0], ah[mt], bh[nt][0], bh[nt][2]);
                mma16816(acc[mt][nt*2+1], ah[mt], bh[nt][1], bh[nt][3]);
            }
    }
}

// ---------------------------------------------------------------------------
// fused score kernel: one CTA = (row-block, u-pass) unit
// grid 2048; ut is the MINOR index so consecutive CTAs share A rows (L2 dedup)
// partial[row] = sum_{u in pass} tanh(hiddens@W1 + b1 + q)[u] * V[u]
// ---------------------------------------------------------------------------
__global__ void __launch_bounds__(NTHR, 1)
score_kernel(const float* __restrict__ b1, const float* __restrict__ V)
{
    extern __shared__ char smem[];
    const uint32_t sb = (uint32_t)__cvta_generic_to_shared(smem);
    const int tid  = threadIdx.x;
    const int lane = tid & 31;
    const int wid  = tid >> 5;
    const int wm   = wid >> 2;      // 0..3  -> M offset 32*wm
    const int wn   = wid & 3;       // 0..3  -> N offset 64*wn
    const int ut     = blockIdx.x & 3;         // 0..3 (minor)
    const int rblock = blockIdx.x >> 2;        // 0..511
    const int row0 = rblock * 128;
    const int b    = rblock >> 4;
    const int u0   = ut * 256;

    float* bqs  = (float*)(smem + OFF_BQ);     // bias+query for this pass (256)
    float* vss  = (float*)(smem + OFF_VS);
    float* srow = (float*)(smem + OFF_SROW);
    for (int i = tid; i < 256; i += NTHR) {
        bqs[i] = b1[u0 + i] + g_query[b * Uu + u0 + i];
        vss[i] = V[u0 + i];
    }
    if (tid < 128) srow[tid] = 0.f;

    // per-lane ldmatrix bases
    const int lrow = lane & 15;
    const int lk16 = (lane & 16);          // 0 or 16 bytes (k-halves)
    const int msk  = (lrow & 7) * 16;      // row-dependent xor mask
    uint32_t a_base[2], b_base[4];
#pragma unroll
    for (int mt = 0; mt < 2; ++mt)
        a_base[mt] = sb + OFF_TILE + (wm * 32 + mt * 16 + lrow) * 128;
#pragma unroll
    for (int nt = 0; nt < 4; ++nt)
        b_base[nt] = sb + OFF_TILE + (wn * 64 + nt * 16 + lrow) * 128;

    float acc[2][8][4];
#pragma unroll
    for (int mt = 0; mt < 2; ++mt)
#pragma unroll
        for (int n = 0; n < 8; ++n)
#pragma unroll
            for (int c = 0; c < 4; ++c) acc[mt][n][c] = 0.f;

    // prologue: double-chunk 0 into buffer 0
    load_dchunk(row0, u0, 0, sb, 0, tid);
    CP_COMMIT();

    for (int ki = 0; ki < KITER; ++ki) {
        const uint32_t bufoff = (uint32_t)(ki & 1) * BUF_SZ;

        CP_WAIT0();
        __syncthreads();   // data for ki visible; buffer ki-1 fully drained

        if (ki + 1 < KITER) {
            load_dchunk(row0, u0, (ki + 1) * 128, sb, bufoff ^ BUF_SZ, tid);
            CP_COMMIT();
        }

        compute_sub(acc, a_base, b_base, msk, lk16,
                    bufoff, bufoff + B_REG);
        compute_sub(acc, a_base, b_base, msk, lk16,
                    bufoff + 16384, bufoff + B_REG + 32768);
    }

    // fused epilogue: tanh(key)*V partial row sums for this u-pass
    float sprt[4];
#pragma unroll
    for (int p = 0; p < 4; ++p) sprt[p] = 0.f;
#pragma unroll
    for (int mt = 0; mt < 2; ++mt)
#pragma unroll
        for (int n8 = 0; n8 < 8; ++n8) {
            const int u = wn * 64 + (n8 >> 1) * 16 + (n8 & 1) * 8 + (lane & 3) * 2;
            const float q0 = bqs[u],     v0 = vss[u];
            const float q1 = bqs[u + 1], v1 = vss[u + 1];
            sprt[mt*2+0] += ftanh(acc[mt][n8][0] + q0) * v0
                          + ftanh(acc[mt][n8][1] + q1) * v1;
            sprt[mt*2+1] += ftanh(acc[mt][n8][2] + q0) * v0
                          + ftanh(acc[mt][n8][3] + q1) * v1;
        }

    // reduce partial sums: quad shuffle then smem atomics across wn warps
    __syncthreads();
#pragma unroll
    for (int p = 0; p < 4; ++p) {
        float v = sprt[p];
        v += __shfl_xor_sync(0xffffffffu, v, 1);
        v += __shfl_xor_sync(0xffffffffu, v, 2);
        if ((lane & 3) == 0) {
            const int r = wm * 32 + (p >> 1) * 16 + (p & 1) * 8 + (lane >> 2);
            atomicAdd(&srow[r], v);
        }
    }
    __syncthreads();
    if (tid < 128) g_spart[ut][row0 + tid] = srow[tid];
}

// ---------------------------------------------------------------------------
// softmax over S per batch (summing the 4 pass partials);
// also zeroes the context region of d_out; weights -> d_out + g_score
// ---------------------------------------------------------------------------
__global__ void softmax_kernel(float* __restrict__ out)
{
    __shared__ float red[256];
    const int b = blockIdx.x;
    const int tid = threadIdx.x;
    float* sc = g_score + b * Ss;

    // zero context region (this batch's rows) before context_kernel atomics
    for (int i = tid; i < Hh; i += 256) out[b * Hh + i] = 0.f;

    float m = -1e30f;
    for (int i = tid; i < Ss; i += 256) {
        const int o = b * Ss + i;
        const float v = g_spart[0][o] + g_spart[1][o] + g_spart[2][o] + g_spart[3][o];
        sc[i] = v;
        m = fmaxf(m, v);
    }
    red[tid] = m;
    __syncthreads();
    for (int s = 128; s > 0; s >>= 1) {
        if (tid < s) red[tid] = fmaxf(red[tid], red[tid + s]);
        __syncthreads();
    }
    m = red[0];
    __syncthreads();

    float sum = 0.f;
    for (int i = tid; i < Ss; i += 256) {
        float e = expf(sc[i] - m);
        sc[i] = e;
        sum += e;
    }
    red[tid] = sum;
    __syncthreads();
    for (int s = 128; s > 0; s >>= 1) {
        if (tid < s) red[tid] += red[tid + s];
        __syncthreads();
    }
    const float inv = 1.f / red[0];
    __syncthreads();

    float* wout = out + Bb * Hh;
    for (int i = tid; i < Ss; i += 256) {
        const float w = sc[i] * inv;
        sc[i] = w;
        wout[b * Ss + i] = w;
    }
}

// ---------------------------------------------------------------------------
// context[b,h] = sum_s w[b,s] * hiddens[b,s,h]  (reads fp16 g_a_hi)
// grid (B, 32 s-chunks), block 256; each thread owns 4 h values (uint2)
// ---------------------------------------------------------------------------
__global__ void __launch_bounds__(256)
context_kernel(float* __restrict__ out)
{
    const int b  = blockIdx.x;
    const int s0 = blockIdx.y * (Ss / 32);
    const int h4 = threadIdx.x;                    // 0..255 -> h = h4*4..h4*4+3

    const float* wp = g_score + b * Ss + s0;
    const uint2* hp = (const uint2*)(g_a_hi + (size_t)(b * Ss + s0) * Hh) + h4;

    float a0 = 0.f, a1 = 0.f, a2 = 0.f, a3 = 0.f;
#pragma unroll 8
    for (int s = 0; s < Ss / 32; ++s) {
        const float w = wp[s];
        const uint2 v = hp[(size_t)s * (Hh / 4)];
        const float2 p01 = __half22float2(*reinterpret_cast<const __half2*>(&v.x));
        const float2 p23 = __half22float2(*reinterpret_cast<const __half2*>(&v.y));
        a0 += w * p01.x;
        a1 += w * p01.y;
        a2 += w * p23.x;
        a3 += w * p23.y;
    }
    float* o = out + b * Hh + h4 * 4;
    atomicAdd(o + 0, a0);
    atomicAdd(o + 1, a1);
    atomicAdd(o + 2, a2);
    atomicAdd(o + 3, a3);
}

// ---------------------------------------------------------------------------
extern "C" void kernel_launch(void* const* d_in, const int* in_sizes, int n_in,
                              void* d_out, int out_size)
{
    const float* hidden_t = (const float*)d_in[0];
    const float* hiddens  = (const float*)d_in[1];
    const float* W1       = (const float*)d_in[2];
    const float* b1       = (const float*)d_in[3];
    const float* W2       = (const float*)d_in[4];
    const float* b2       = (const float*)d_in[5];
    const float* V        = (const float*)d_in[6];
    // d_in[7] = bV : constant shift, cancels in softmax -> unused

    float* out = (float*)d_out;

    cudaFuncSetAttribute(score_kernel,
                         cudaFuncAttributeMaxDynamicSharedMemorySize,
                         SMEM_TOTAL);

    prep_kernel<<<NB_PREP, 256>>>(hiddens, W1, hidden_t, W2, b2);
    score_kernel<<<2048, NTHR, SMEM_TOTAL>>>(b1, V);
    softmax_kernel<<<Bb, 256>>>(out);
    context_kernel<<<dim3(Bb, 32), 256>>>(out);
}